// round 4
// baseline (speedup 1.0000x reference)
#include <cuda_runtime.h>
#include <cuda_bf16.h>
#include <stdint.h>

// FuzzyPooling: 2x2 stride-2 pooling with fuzzy membership selection.
// x: (32,64,128,128) fp32 -> out: (32,64,64,64) fp32
//
// mu1 = tri(v,1.5,1.5); mu2 = tri(v,3.0,1.5); mu3 == mu2 (identical
// constants), argmax takes first max -> sel = (s1 >= s2) ? mu1 : mu2.
// Memberships appear only in scale-invariant positions (compare, ratio,
// zero-test) -> use unnormalized t1(v)=max(min(v,3-v),0), t2(v)=t1(v-1.5).
//
// R4: persistent grid (1 resident wave, 148x4 CTAs), grid-stride over
// 8-output tiles: 8 front-batched float4 loads (MLP_p1=8), 2 float4 stores.
// Keeps the chip-wide outstanding-load pool full for the whole kernel
// instead of draining it at every one of ~7 wave boundaries.

#define H_IN   128
#define W_IN   128
#define HO     64
#define WO     64
#define BC     (32 * 64)
#define N_OUT  (BC * HO * WO)       // 8,388,608
#define TOTAL_OCTS (N_OUT / 8)      // 1,048,576
#define GRID_BLOCKS (148 * 4)       // one resident wave at 4 CTAs/SM

__device__ __forceinline__ void memb(float v, float& u1, float& u2) {
    float w = v - 1.5f;
    u1 = fmaxf(fminf(v, 3.0f - v), 0.0f);
    u2 = fmaxf(fminf(w, 3.0f - w), 0.0f);
}

__device__ __forceinline__ float fuzzy_patch(float a, float b, float c, float d) {
    float m1a, m2a, m1b, m2b, m1c, m2c, m1d, m2d;
    memb(a, m1a, m2a);
    memb(b, m1b, m2b);
    memb(c, m1c, m2c);
    memb(d, m1d, m2d);

    float s1 = (m1a + m1b) + (m1c + m1d);
    float s2 = (m2a + m2b) + (m2c + m2d);
    bool pick1 = (s1 >= s2);

    float ma = pick1 ? m1a : m2a;
    float mb = pick1 ? m1b : m2b;
    float mc = pick1 ? m1c : m2c;
    float md = pick1 ? m1d : m2d;

    float ta = ma * a, tb = mb * b, tc = mc * c, td = md * d;
    float den = (ta + tb) + (tc + td);
    float num = fmaf(ta, a, fmaf(tb, b, fmaf(tc, c, td * d)));

    float r = __fdividef(num, den);      // rcp + mul; den==0 handled below
    return (den == 0.0f) ? 0.0f : r;
}

__global__ __launch_bounds__(256, 4)
void fuzzy_pool_kernel(const float* __restrict__ x, float* __restrict__ out) {
    const int T = GRID_BLOCKS * 256;
    for (int q = blockIdx.x * blockDim.x + threadIdx.x; q < TOTAL_OCTS; q += T) {
        int w8 = q & 7;             // oct index along Wo (WO/8 = 8)
        int ho = (q >> 3) & 63;     // output row
        int bc = q >> 9;            // plane

        const float4* r0 = reinterpret_cast<const float4*>(
            x + (size_t)bc * (H_IN * W_IN) + (2 * ho) * W_IN + 16 * w8);
        const float4* r1 = r0 + (W_IN / 4);

        // 8 independent loads, all in flight before any compute
        float4 a0 = __ldcs(r0),     a1 = __ldcs(r0 + 1);
        float4 a2 = __ldcs(r0 + 2), a3 = __ldcs(r0 + 3);
        float4 b0 = __ldcs(r1),     b1 = __ldcs(r1 + 1);
        float4 b2 = __ldcs(r1 + 2), b3 = __ldcs(r1 + 3);

        float4 o0, o1;
        o0.x = fuzzy_patch(a0.x, a0.y, b0.x, b0.y);
        o0.y = fuzzy_patch(a0.z, a0.w, b0.z, b0.w);
        o0.z = fuzzy_patch(a1.x, a1.y, b1.x, b1.y);
        o0.w = fuzzy_patch(a1.z, a1.w, b1.z, b1.w);
        o1.x = fuzzy_patch(a2.x, a2.y, b2.x, b2.y);
        o1.y = fuzzy_patch(a2.z, a2.w, b2.z, b2.w);
        o1.z = fuzzy_patch(a3.x, a3.y, b3.x, b3.y);
        o1.w = fuzzy_patch(a3.z, a3.w, b3.z, b3.w);

        float* ob = out + (size_t)bc * (HO * WO) + ho * WO + 8 * w8;
        __stcs(reinterpret_cast<float4*>(ob), o0);
        __stcs(reinterpret_cast<float4*>(ob) + 1, o1);
    }
}

extern "C" void kernel_launch(void* const* d_in, const int* in_sizes, int n_in,
                              void* d_out, int out_size) {
    const float* x = (const float*)d_in[0];
    float* out = (float*)d_out;
    fuzzy_pool_kernel<<<GRID_BLOCKS, 256>>>(x, out);
}

// round 5
// speedup vs baseline: 1.0970x; 1.0970x over previous
#include <cuda_runtime.h>
#include <cuda_bf16.h>
#include <stdint.h>

// FuzzyPooling: 2x2 stride-2 pooling with fuzzy membership selection.
// x: (32,64,128,128) fp32 -> out: (32,64,64,64) fp32
//
// mu1 = tri(v,1.5,1.5); mu2 = tri(v,3.0,1.5); mu3 == mu2 (identical
// constants), argmax takes first max -> sel = (s1 >= s2) ? mu1 : mu2.
// Memberships appear only in scale-invariant positions (compare, ratio,
// zero-test) -> unnormalized t1(v)=max(min(v,3-v),0), t2(v)=t1(v-1.5).
//
// R5: identical to R3 except stores are evict-NORMAL (no .cs).
// Output (33.6 MB) fits in the 126 MB L2; reads stay evict-first (.cs).
// Goal: keep output resident in L2 so DRAM sees a nearly pure read
// stream (no write drain / bus turnaround during the kernel, and ~zero
// steady-state write traffic across graph replays).

#define H_IN   128
#define W_IN   128
#define HO     64
#define WO     64
#define BC     (32 * 64)
#define N_OUT  (BC * HO * WO)     // 8,388,608

__device__ __forceinline__ void memb(float v, float& u1, float& u2) {
    float w = v - 1.5f;
    u1 = fmaxf(fminf(v, 3.0f - v), 0.0f);
    u2 = fmaxf(fminf(w, 3.0f - w), 0.0f);
}

__device__ __forceinline__ float fuzzy_patch(float a, float b, float c, float d) {
    float m1a, m2a, m1b, m2b, m1c, m2c, m1d, m2d;
    memb(a, m1a, m2a);
    memb(b, m1b, m2b);
    memb(c, m1c, m2c);
    memb(d, m1d, m2d);

    float s1 = (m1a + m1b) + (m1c + m1d);
    float s2 = (m2a + m2b) + (m2c + m2d);
    bool pick1 = (s1 >= s2);

    float ma = pick1 ? m1a : m2a;
    float mb = pick1 ? m1b : m2b;
    float mc = pick1 ? m1c : m2c;
    float md = pick1 ? m1d : m2d;

    float ta = ma * a, tb = mb * b, tc = mc * c, td = md * d;
    float den = (ta + tb) + (tc + td);
    float num = fmaf(ta, a, fmaf(tb, b, fmaf(tc, c, td * d)));

    float r = __fdividef(num, den);      // rcp + mul; den==0 handled below
    return (den == 0.0f) ? 0.0f : r;
}

__global__ __launch_bounds__(256)
void fuzzy_pool_kernel(const float* __restrict__ x, float* __restrict__ out) {
    // 4 outputs/thread: 4 independent float4 loads up front (MLP=4).
    int tid = blockIdx.x * blockDim.x + threadIdx.x;

    int wq  = tid & 15;            // quad index along Wo (WO/4 = 16)
    int ho  = (tid >> 4) & 63;     // output row
    int bc  = tid >> 10;           // plane

    const float4* base0 = reinterpret_cast<const float4*>(
        x + (size_t)bc * (H_IN * W_IN) + (2 * ho) * W_IN + 8 * wq);
    const float4* base1 = base0 + (W_IN / 4);

    // streaming loads (evict-first): use-once data must not displace
    // the L2-resident output lines
    float4 a0 = __ldcs(base0);
    float4 a1 = __ldcs(base0 + 1);
    float4 b0 = __ldcs(base1);
    float4 b1 = __ldcs(base1 + 1);

    float4 o;
    o.x = fuzzy_patch(a0.x, a0.y, b0.x, b0.y);
    o.y = fuzzy_patch(a0.z, a0.w, b0.z, b0.w);
    o.z = fuzzy_patch(a1.x, a1.y, b1.x, b1.y);
    o.w = fuzzy_patch(a1.z, a1.w, b1.z, b1.w);

    // evict-normal store: let the 33.6 MB output live in L2
    *reinterpret_cast<float4*>(
        out + (size_t)bc * (HO * WO) + ho * WO + 4 * wq) = o;
}

extern "C" void kernel_launch(void* const* d_in, const int* in_sizes, int n_in,
                              void* d_out, int out_size) {
    const float* x = (const float*)d_in[0];
    float* out = (float*)d_out;
    int threads = 256;
    int total = N_OUT / 4;                  // 2,097,152
    int blocks = total / threads;           // 8192 exactly
    fuzzy_pool_kernel<<<blocks, threads>>>(x, out);
}

// round 6
// speedup vs baseline: 1.1182x; 1.0193x over previous
#include <cuda_runtime.h>
#include <cuda_bf16.h>
#include <stdint.h>

// FuzzyPooling: 2x2 stride-2 pooling with fuzzy membership selection.
// x: (32,64,128,128) fp32 -> out: (32,64,64,64) fp32
//
// mu1 = tri(v,1.5,1.5); mu2 = tri(v,3.0,1.5); mu3 == mu2 (identical
// constants), argmax takes first max -> sel = (s1 >= s2) ? mu1 : mu2.
// Memberships appear only in scale-invariant positions (compare, ratio,
// zero-test) -> unnormalized t1(v)=max(min(v,3-v),0), t2(v)=t1(v-1.5).
//
// R6 = R3 (best: 26.0us, .cs loads AND stores) + collapsed addressing:
//   out float offset  = 4*tid            (output is contiguous in tid)
//   in  float offset  = 16*tid - 8*(tid&15)
// (tid = bc*1024 + ho*16 + wq; in = bc*16384 + ho*256 + wq*8
//  = 8*(2*tid - wq).)  Saves IMAD/shift chains and a register.

#define N_OUT  (32 * 64 * 64 * 64)   // 8,388,608

__device__ __forceinline__ void memb(float v, float& u1, float& u2) {
    float w = v - 1.5f;
    u1 = fmaxf(fminf(v, 3.0f - v), 0.0f);
    u2 = fmaxf(fminf(w, 3.0f - w), 0.0f);
}

__device__ __forceinline__ float fuzzy_patch(float a, float b, float c, float d) {
    float m1a, m2a, m1b, m2b, m1c, m2c, m1d, m2d;
    memb(a, m1a, m2a);
    memb(b, m1b, m2b);
    memb(c, m1c, m2c);
    memb(d, m1d, m2d);

    float s1 = (m1a + m1b) + (m1c + m1d);
    float s2 = (m2a + m2b) + (m2c + m2d);
    bool pick1 = (s1 >= s2);

    float ma = pick1 ? m1a : m2a;
    float mb = pick1 ? m1b : m2b;
    float mc = pick1 ? m1c : m2c;
    float md = pick1 ? m1d : m2d;

    float ta = ma * a, tb = mb * b, tc = mc * c, td = md * d;
    float den = (ta + tb) + (tc + td);
    float num = fmaf(ta, a, fmaf(tb, b, fmaf(tc, c, td * d)));

    float r = __fdividef(num, den);      // rcp + mul; den==0 handled below
    return (den == 0.0f) ? 0.0f : r;
}

__global__ __launch_bounds__(256)
void fuzzy_pool_kernel(const float* __restrict__ x, float* __restrict__ out) {
    unsigned tid = blockIdx.x * blockDim.x + threadIdx.x;   // < 2,097,152

    // collapsed offsets (all fit comfortably in 32 bits: max in-offset
    // float index = 33,554,424 < 2^25)
    unsigned in_off  = 16u * tid - 8u * (tid & 15u);  // float index of row0
    unsigned out_off = 4u * tid;                      // float index

    const float4* r0 = reinterpret_cast<const float4*>(x + in_off);
    const float4* r1 = r0 + 32;                       // +128 floats (next row)

    // 4 independent streaming loads in flight before any compute
    float4 a0 = __ldcs(r0);
    float4 a1 = __ldcs(r0 + 1);
    float4 b0 = __ldcs(r1);
    float4 b1 = __ldcs(r1 + 1);

    float4 o;
    o.x = fuzzy_patch(a0.x, a0.y, b0.x, b0.y);
    o.y = fuzzy_patch(a0.z, a0.w, b0.z, b0.w);
    o.z = fuzzy_patch(a1.x, a1.y, b1.x, b1.y);
    o.w = fuzzy_patch(a1.z, a1.w, b1.z, b1.w);

    __stcs(reinterpret_cast<float4*>(out + out_off), o);
}

extern "C" void kernel_launch(void* const* d_in, const int* in_sizes, int n_in,
                              void* d_out, int out_size) {
    const float* x = (const float*)d_in[0];
    float* out = (float*)d_out;
    int threads = 256;
    int blocks = (N_OUT / 4) / threads;   // 8192 exactly
    fuzzy_pool_kernel<<<blocks, threads>>>(x, out);
}